// round 1
// baseline (speedup 1.0000x reference)
#include <cuda_runtime.h>
#include <cstddef>

#define BATCH 2
#define SEQ   2048
#define EMB   1024
#define NH    16
#define HD    64
#define E3    (3*EMB)          // 3072
#define MTOT  (BATCH*SEQ)      // 4096
#define ATT_SCALE 0.125f       // 1/sqrt(64)

// Scratch (static device allocations are allowed)
__device__ float g_qkv[(size_t)MTOT * E3];   // [4096][3072]
__device__ float g_ctx[(size_t)MTOT * EMB];  // [4096][1024]

// ---------------------------------------------------------------------------
// GEMM: C[M][N] = A[M][K] @ W[N][K]^T + bias[N]
// 128x128 tile, 256 threads, 8x8 micro (split 4+4), K-step 16.
// ---------------------------------------------------------------------------
__global__ __launch_bounds__(256) void gemm_bias_kernel(
    const float* __restrict__ A, const float* __restrict__ W,
    const float* __restrict__ bias, float* __restrict__ C,
    int M, int N, int K)
{
    __shared__ float As[128][17];
    __shared__ float Ws[128][17];

    const int tid = threadIdx.x;
    const int ty  = tid >> 4;       // 0..15
    const int tx  = tid & 15;       // 0..15
    const int m0  = blockIdx.y * 128;
    const int n0  = blockIdx.x * 128;

    const int rb0 = ty * 4, rb1 = ty * 4 + 64;
    const int cb0 = tx * 4, cb1 = tx * 4 + 64;

    float acc[8][8];
#pragma unroll
    for (int i = 0; i < 8; i++)
#pragma unroll
        for (int j = 0; j < 8; j++) acc[i][j] = 0.0f;

    for (int k0 = 0; k0 < K; k0 += 16) {
#pragma unroll
        for (int l = 0; l < 2; l++) {
            int s   = tid + l * 256;
            int row = s >> 2;
            int c4  = (s & 3) * 4;
            float4 va = *(const float4*)(A + (size_t)(m0 + row) * K + k0 + c4);
            As[row][c4 + 0] = va.x; As[row][c4 + 1] = va.y;
            As[row][c4 + 2] = va.z; As[row][c4 + 3] = va.w;
            float4 vw = *(const float4*)(W + (size_t)(n0 + row) * K + k0 + c4);
            Ws[row][c4 + 0] = vw.x; Ws[row][c4 + 1] = vw.y;
            Ws[row][c4 + 2] = vw.z; Ws[row][c4 + 3] = vw.w;
        }
        __syncthreads();

#pragma unroll
        for (int kk = 0; kk < 16; kk++) {
            float a[8], b[8];
#pragma unroll
            for (int i = 0; i < 4; i++) {
                a[i]     = As[rb0 + i][kk];
                a[i + 4] = As[rb1 + i][kk];
                b[i]     = Ws[cb0 + i][kk];
                b[i + 4] = Ws[cb1 + i][kk];
            }
#pragma unroll
            for (int i = 0; i < 8; i++)
#pragma unroll
                for (int j = 0; j < 8; j++)
                    acc[i][j] += a[i] * b[j];
        }
        __syncthreads();
    }

#pragma unroll
    for (int u = 0; u < 2; u++) {
#pragma unroll
        for (int i = 0; i < 4; i++) {
            int r = m0 + (u ? rb1 : rb0) + i;
#pragma unroll
            for (int v = 0; v < 2; v++) {
#pragma unroll
                for (int j = 0; j < 4; j++) {
                    int c = n0 + (v ? cb1 : cb0) + j;
                    C[(size_t)r * N + c] = acc[u * 4 + i][v * 4 + j] + bias[c];
                }
            }
        }
    }
}

// ---------------------------------------------------------------------------
// Flash-style attention: CTA = (qtile of 64, head, batch). Streams K/V in
// 64-row tiles. qkv layout: [b*S + s][3072], q at +h*64, k at +1024+h*64,
// v at +2048+h*64. Output ctx: [b*S + s][1024] at +h*64.
// ---------------------------------------------------------------------------
#define QPAD 64
#define KPAD 65
#define VPAD 64
#define ATT_SMEM ((64*QPAD + 64*KPAD + 64*VPAD) * 4)

__global__ __launch_bounds__(256) void attn_kernel(
    const float* __restrict__ qkv, float* __restrict__ ctx)
{
    extern __shared__ float sh[];
    float* qs = sh;                  // [64][64]
    float* ks = sh + 64 * QPAD;      // [64][65]  (reused as P tile)
    float* vs = ks + 64 * KPAD;      // [64][64]

    const int tid = threadIdx.x;
    const int ty  = tid >> 4;
    const int tx  = tid & 15;
    const int q0  = blockIdx.x * 64;
    const int h   = blockIdx.y;
    const int b   = blockIdx.z;

    const float* qbase = qkv + (size_t)(b * SEQ) * E3 + h * HD;
    const float* kbase = qbase + EMB;
    const float* vbase = qbase + 2 * EMB;

    // Load + pre-scale Q tile
#pragma unroll
    for (int l = 0; l < 4; l++) {
        int s   = tid + l * 256;
        int row = s >> 4;
        int c4  = (s & 15) * 4;
        float4 v = *(const float4*)(qbase + (size_t)(q0 + row) * E3 + c4);
        qs[row * QPAD + c4 + 0] = v.x * ATT_SCALE;
        qs[row * QPAD + c4 + 1] = v.y * ATT_SCALE;
        qs[row * QPAD + c4 + 2] = v.z * ATT_SCALE;
        qs[row * QPAD + c4 + 3] = v.w * ATT_SCALE;
    }

    const int r0 = ty * 4;
    const int c0 = tx * 4;

    float o[4][4];
    float mrow[4], lrow[4];
#pragma unroll
    for (int i = 0; i < 4; i++) {
        mrow[i] = -1e30f;
        lrow[i] = 0.0f;
#pragma unroll
        for (int j = 0; j < 4; j++) o[i][j] = 0.0f;
    }

    for (int kt = 0; kt < SEQ; kt += 64) {
        __syncthreads();   // protects qs (iter 0) and ks/vs reuse (iters > 0)

        // Load K and V tiles
#pragma unroll
        for (int l = 0; l < 4; l++) {
            int s   = tid + l * 256;
            int row = s >> 4;
            int c4  = (s & 15) * 4;
            float4 kv = *(const float4*)(kbase + (size_t)(kt + row) * E3 + c4);
            ks[row * KPAD + c4 + 0] = kv.x; ks[row * KPAD + c4 + 1] = kv.y;
            ks[row * KPAD + c4 + 2] = kv.z; ks[row * KPAD + c4 + 3] = kv.w;
            float4 vv = *(const float4*)(vbase + (size_t)(kt + row) * E3 + c4);
            vs[row * VPAD + c4 + 0] = vv.x; vs[row * VPAD + c4 + 1] = vv.y;
            vs[row * VPAD + c4 + 2] = vv.z; vs[row * VPAD + c4 + 3] = vv.w;
        }
        __syncthreads();

        // Scores: sc = (Q*scale) @ K^T  (64x64, 4x4 micro)
        float sc[4][4];
#pragma unroll
        for (int i = 0; i < 4; i++)
#pragma unroll
            for (int j = 0; j < 4; j++) sc[i][j] = 0.0f;

#pragma unroll 8
        for (int d = 0; d < 64; d++) {
            float a[4], bb[4];
#pragma unroll
            for (int i = 0; i < 4; i++) a[i]  = qs[(r0 + i) * QPAD + d];
#pragma unroll
            for (int j = 0; j < 4; j++) bb[j] = ks[(c0 + j) * KPAD + d];
#pragma unroll
            for (int i = 0; i < 4; i++)
#pragma unroll
                for (int j = 0; j < 4; j++)
                    sc[i][j] += a[i] * bb[j];
        }
        __syncthreads();   // everyone done reading ks before it becomes P

        // Online softmax (row stats shared across the 16 tx threads of a row
        // via intra-half-warp shuffles; offsets 1,2,4,8 stay within 16 lanes)
#pragma unroll
        for (int i = 0; i < 4; i++) {
            float mx = fmaxf(fmaxf(sc[i][0], sc[i][1]), fmaxf(sc[i][2], sc[i][3]));
#pragma unroll
            for (int off = 8; off >= 1; off >>= 1)
                mx = fmaxf(mx, __shfl_xor_sync(0xffffffffu, mx, off, 32));
            float newm  = fmaxf(mrow[i], mx);
            float alpha = __expf(mrow[i] - newm);
            mrow[i] = newm;
            float rsum = 0.0f;
#pragma unroll
            for (int j = 0; j < 4; j++) {
                sc[i][j] = __expf(sc[i][j] - newm);
                rsum += sc[i][j];
            }
#pragma unroll
            for (int off = 8; off >= 1; off >>= 1)
                rsum += __shfl_xor_sync(0xffffffffu, rsum, off, 32);
            lrow[i] = lrow[i] * alpha + rsum;
#pragma unroll
            for (int j = 0; j < 4; j++) o[i][j] *= alpha;
        }

        // Write P into the ks buffer
#pragma unroll
        for (int i = 0; i < 4; i++)
#pragma unroll
            for (int j = 0; j < 4; j++)
                ks[(r0 + i) * KPAD + c0 + j] = sc[i][j];
        __syncthreads();

        // O += P @ V  (64x64x64)
#pragma unroll 8
        for (int k = 0; k < 64; k++) {
            float a[4], bb[4];
#pragma unroll
            for (int i = 0; i < 4; i++) a[i]  = ks[(r0 + i) * KPAD + k];
#pragma unroll
            for (int j = 0; j < 4; j++) bb[j] = vs[k * VPAD + c0 + j];
#pragma unroll
            for (int i = 0; i < 4; i++)
#pragma unroll
                for (int j = 0; j < 4; j++)
                    o[i][j] += a[i] * bb[j];
        }
    }

    // Normalize and write ctx
#pragma unroll
    for (int i = 0; i < 4; i++) {
        float inv = 1.0f / lrow[i];
        size_t base = (size_t)(b * SEQ + q0 + r0 + i) * EMB + h * HD + c0;
#pragma unroll
        for (int j = 0; j < 4; j++)
            ctx[base + j] = o[i][j] * inv;
    }
}

// ---------------------------------------------------------------------------
extern "C" void kernel_launch(void* const* d_in, const int* in_sizes, int n_in,
                              void* d_out, int out_size)
{
    const float* x      = (const float*)d_in[0];
    const float* w_qkv  = (const float*)d_in[1];
    const float* w_out  = (const float*)d_in[2];
    const float* b_qkv  = (const float*)d_in[3];
    const float* b_out  = (const float*)d_in[4];
    float* out = (float*)d_out;

    float *qkv_s = nullptr, *ctx_s = nullptr;
    cudaGetSymbolAddress((void**)&qkv_s, g_qkv);
    cudaGetSymbolAddress((void**)&ctx_s, g_ctx);

    cudaFuncSetAttribute(attn_kernel,
                         cudaFuncAttributeMaxDynamicSharedMemorySize, ATT_SMEM);

    // QKV projection: [4096,1024] @ [3072,1024]^T -> [4096,3072]
    gemm_bias_kernel<<<dim3(E3 / 128, MTOT / 128), 256>>>(
        x, w_qkv, b_qkv, qkv_s, MTOT, E3, EMB);

    // Attention
    attn_kernel<<<dim3(SEQ / 64, NH, BATCH), 256, ATT_SMEM>>>(qkv_s, ctx_s);

    // Output projection: [4096,1024] @ [1024,1024]^T -> [4096,1024]
    gemm_bias_kernel<<<dim3(EMB / 128, MTOT / 128), 256>>>(
        ctx_s, w_out, b_out, out, MTOT, EMB, EMB);
}

// round 3
// speedup vs baseline: 1.5130x; 1.5130x over previous
#include <cuda_runtime.h>
#include <cuda_bf16.h>
#include <cstdint>
#include <cstddef>

#define BATCH 2
#define SEQ   2048
#define EMB   1024
#define NH    16
#define HD    64
#define E3    (3*EMB)          // 3072
#define MTOT  (BATCH*SEQ)      // 4096
#define ATT_SCALE 0.125f       // 1/sqrt(64)

// Scratch (static device allocations are allowed)
__device__ float g_qkv[(size_t)MTOT * E3];   // [4096][3072]
__device__ float g_ctx[(size_t)MTOT * EMB];  // [4096][1024]

// ===========================================================================
// Warp-MMA helpers (non-'a' PTX: works on plain sm_103 target)
// ===========================================================================
__device__ __forceinline__ uint32_t cvta_smem(const void* p) {
    uint32_t a;
    asm("{ .reg .u64 t; cvta.to.shared.u64 t, %1; cvt.u32.u64 %0, t; }"
        : "=r"(a) : "l"(p));
    return a;
}

__device__ __forceinline__ void ldsm_x4(uint32_t& r0, uint32_t& r1,
                                        uint32_t& r2, uint32_t& r3, uint32_t addr) {
    asm volatile("ldmatrix.sync.aligned.m8n8.x4.shared.b16 {%0,%1,%2,%3}, [%4];"
                 : "=r"(r0), "=r"(r1), "=r"(r2), "=r"(r3) : "r"(addr));
}
__device__ __forceinline__ void ldsm_x2(uint32_t& r0, uint32_t& r1, uint32_t addr) {
    asm volatile("ldmatrix.sync.aligned.m8n8.x2.shared.b16 {%0,%1}, [%2];"
                 : "=r"(r0), "=r"(r1) : "r"(addr));
}

__device__ __forceinline__ void mma_bf16(float* d, const uint32_t* a, const uint32_t* b) {
    asm volatile(
        "mma.sync.aligned.m16n8k16.row.col.f32.bf16.bf16.f32 "
        "{%0,%1,%2,%3}, {%4,%5,%6,%7}, {%8,%9}, {%0,%1,%2,%3};"
        : "+f"(d[0]), "+f"(d[1]), "+f"(d[2]), "+f"(d[3])
        : "r"(a[0]), "r"(a[1]), "r"(a[2]), "r"(a[3]), "r"(b[0]), "r"(b[1]));
}

// Pack two floats as bf16x2 (memory order: lo half = first arg)
__device__ __forceinline__ uint32_t pack_bf16x2(float a, float b) {
    uint32_t r;
    asm("cvt.rn.bf16x2.f32 %0, %1, %2;" : "=r"(r) : "f"(b), "f"(a));
    return r;
}
__device__ __forceinline__ float bf16_hi_val(float x) {
    // round-to-nearest bf16 then back to fp32
    uint32_t r;
    asm("{ .reg .b16 h; cvt.rn.bf16.f32 h, %1; mov.b32 %0, {h, h}; }" : "=r"(r) : "f"(x));
    return __uint_as_float(r & 0xFFFF0000u) ; // hi half holds the bf16 bits
}

// ===========================================================================
// bf16-split GEMM: C[M][N] = A[M][K] @ W[N][K]^T + bias[N]
// 128x128 CTA tile, 8 warps (4m x 2n), warp tile 32x64, K-chunk 32.
// Smem tiles: [128 rows][40 bf16] (80B stride, ldmatrix conflict-free).
// ===========================================================================
#define SROW   40                       // bf16 elements per smem row (80B)
#define TILE_B (128 * SROW * 2)         // 10240 bytes per tile
#define OFF_AHI 0
#define OFF_ALO (TILE_B)
#define OFF_BHI (2 * TILE_B)
#define OFF_BLO (3 * TILE_B)

__global__ __launch_bounds__(256)
void gemm_mma_kernel(const float* __restrict__ A, const float* __restrict__ W,
                     const float* __restrict__ bias, float* __restrict__ C,
                     int M, int N, int K)
{
    __shared__ __align__(16) char smem[4 * TILE_B];
    const uint32_t smem_u = cvta_smem(smem);

    const int tid  = threadIdx.x;
    const int wid  = tid >> 5;
    const int lane = tid & 31;
    const int wm   = wid & 3;          // 0..3  (m block of 32)
    const int wn   = wid >> 2;         // 0..1  (n block of 64)
    const int m0   = blockIdx.y * 128;
    const int n0   = blockIdx.x * 128;

    float acc[2][8][4];
#pragma unroll
    for (int mi = 0; mi < 2; mi++)
#pragma unroll
        for (int ni = 0; ni < 8; ni++)
#pragma unroll
            for (int r = 0; r < 4; r++) acc[mi][ni][r] = 0.0f;

    const int nchunks = K >> 5;

    // prefetch registers: 4 float4 from A, 4 from B per thread per chunk
    float4 pA[4], pB[4];

    // thread -> (row, col4) map for loading a 128x32 chunk with 256 threads
    int lrow[4], lcol[4];
#pragma unroll
    for (int it = 0; it < 4; it++) {
        int idx = tid + it * 256;
        lrow[it] = idx >> 3;
        lcol[it] = (idx & 7) * 4;
    }

#pragma unroll 1
    for (int it = 0; it < 4; it++) {
        pA[it] = *(const float4*)(A + (size_t)(m0 + lrow[it]) * K + lcol[it]);
        pB[it] = *(const float4*)(W + (size_t)(n0 + lrow[it]) * K + lcol[it]);
    }

    for (int c = 0; c < nchunks; c++) {
        __syncthreads();   // previous chunk fully consumed

        // split-convert prefetched data into smem
#pragma unroll
        for (int it = 0; it < 4; it++) {
            uint32_t base = (uint32_t)(lrow[it] * (SROW * 2) + lcol[it] * 2);
            float4 v = pA[it];
            float hx = bf16_hi_val(v.x), hy = bf16_hi_val(v.y);
            float hz = bf16_hi_val(v.z), hw = bf16_hi_val(v.w);
            uint2 hi = make_uint2(pack_bf16x2(hx, hy), pack_bf16x2(hz, hw));
            uint2 lo = make_uint2(pack_bf16x2(v.x - hx, v.y - hy),
                                  pack_bf16x2(v.z - hz, v.w - hw));
            *(uint2*)(smem + OFF_AHI + base) = hi;
            *(uint2*)(smem + OFF_ALO + base) = lo;

            v = pB[it];
            hx = bf16_hi_val(v.x); hy = bf16_hi_val(v.y);
            hz = bf16_hi_val(v.z); hw = bf16_hi_val(v.w);
            hi = make_uint2(pack_bf16x2(hx, hy), pack_bf16x2(hz, hw));
            lo = make_uint2(pack_bf16x2(v.x - hx, v.y - hy),
                            pack_bf16x2(v.z - hz, v.w - hw));
            *(uint2*)(smem + OFF_BHI + base) = hi;
            *(uint2*)(smem + OFF_BLO + base) = lo;
        }
        __syncthreads();

        // prefetch next chunk (overlaps with MMA below)
        if (c + 1 < nchunks) {
            const int k0 = (c + 1) << 5;
#pragma unroll
            for (int it = 0; it < 4; it++) {
                pA[it] = *(const float4*)(A + (size_t)(m0 + lrow[it]) * K + k0 + lcol[it]);
                pB[it] = *(const float4*)(W + (size_t)(n0 + lrow[it]) * K + k0 + lcol[it]);
            }
        }

        // MMA over the 32-deep chunk: 2 k-steps of 16
#pragma unroll
        for (int ks = 0; ks < 2; ks++) {
            const uint32_t kbyte = (uint32_t)(ks * 16 * 2);

            uint32_t a_hi[2][4], a_lo[2][4];
#pragma unroll
            for (int mi = 0; mi < 2; mi++) {
                uint32_t arow = (uint32_t)(wm * 32 + mi * 16 + (lane & 15));
                uint32_t aoff = arow * (SROW * 2) + kbyte + ((lane >> 4) << 4);
                ldsm_x4(a_hi[mi][0], a_hi[mi][1], a_hi[mi][2], a_hi[mi][3],
                        smem_u + OFF_AHI + aoff);
                ldsm_x4(a_lo[mi][0], a_lo[mi][1], a_lo[mi][2], a_lo[mi][3],
                        smem_u + OFF_ALO + aoff);
            }

#pragma unroll
            for (int nh = 0; nh < 2; nh++) {
                uint32_t b_hi[4][2], b_lo[4][2];
#pragma unroll
                for (int nq = 0; nq < 4; nq++) {
                    uint32_t brow = (uint32_t)(wn * 64 + nh * 32 + nq * 8 + (lane & 7));
                    uint32_t boff = brow * (SROW * 2) + kbyte + (((lane >> 3) & 1) << 4);
                    ldsm_x2(b_hi[nq][0], b_hi[nq][1], smem_u + OFF_BHI + boff);
                    ldsm_x2(b_lo[nq][0], b_lo[nq][1], smem_u + OFF_BLO + boff);
                }
#pragma unroll
                for (int mi = 0; mi < 2; mi++)
#pragma unroll
                    for (int nq = 0; nq < 4; nq++) {
                        float* d = acc[mi][nh * 4 + nq];
                        mma_bf16(d, a_hi[mi], b_hi[nq]);
                        mma_bf16(d, a_hi[mi], b_lo[nq]);
                        mma_bf16(d, a_lo[mi], b_hi[nq]);
                    }
            }
        }
    }

    // Epilogue: write acc + bias
    const int rbase = m0 + wm * 32 + (lane >> 2);
    const int cbase = n0 + wn * 64 + (lane & 3) * 2;
#pragma unroll
    for (int mi = 0; mi < 2; mi++) {
#pragma unroll
        for (int ni = 0; ni < 8; ni++) {
            int cc = cbase + ni * 8;
            float2 bv = *(const float2*)(bias + cc);
            int r = rbase + mi * 16;
            float2 o0 = make_float2(acc[mi][ni][0] + bv.x, acc[mi][ni][1] + bv.y);
            *(float2*)(C + (size_t)r * N + cc) = o0;
            float2 o1 = make_float2(acc[mi][ni][2] + bv.x, acc[mi][ni][3] + bv.y);
            *(float2*)(C + (size_t)(r + 8) * N + cc) = o1;
        }
    }
}

// ---------------------------------------------------------------------------
// Flash-style attention (unchanged, SIMT): CTA = (qtile 64, head, batch).
// ---------------------------------------------------------------------------
#define QPAD 64
#define KPAD 65
#define VPAD 64
#define ATT_SMEM ((64*QPAD + 64*KPAD + 64*VPAD) * 4)

__global__ __launch_bounds__(256) void attn_kernel(
    const float* __restrict__ qkv, float* __restrict__ ctx)
{
    extern __shared__ float sh[];
    float* qs = sh;
    float* ks = sh + 64 * QPAD;
    float* vs = ks + 64 * KPAD;

    const int tid = threadIdx.x;
    const int ty  = tid >> 4;
    const int tx  = tid & 15;
    const int q0  = blockIdx.x * 64;
    const int h   = blockIdx.y;
    const int b   = blockIdx.z;

    const float* qbase = qkv + (size_t)(b * SEQ) * E3 + h * HD;
    const float* kbase = qbase + EMB;
    const float* vbase = qbase + 2 * EMB;

#pragma unroll
    for (int l = 0; l < 4; l++) {
        int s   = tid + l * 256;
        int row = s >> 4;
        int c4  = (s & 15) * 4;
        float4 v = *(const float4*)(qbase + (size_t)(q0 + row) * E3 + c4);
        qs[row * QPAD + c4 + 0] = v.x * ATT_SCALE;
        qs[row * QPAD + c4 + 1] = v.y * ATT_SCALE;
        qs[row * QPAD + c4 + 2] = v.z * ATT_SCALE;
        qs[row * QPAD + c4 + 3] = v.w * ATT_SCALE;
    }

    const int r0 = ty * 4;
    const int c0 = tx * 4;

    float o[4][4];
    float mrow[4], lrow[4];
#pragma unroll
    for (int i = 0; i < 4; i++) {
        mrow[i] = -1e30f;
        lrow[i] = 0.0f;
#pragma unroll
        for (int j = 0; j < 4; j++) o[i][j] = 0.0f;
    }

    for (int kt = 0; kt < SEQ; kt += 64) {
        __syncthreads();
#pragma unroll
        for (int l = 0; l < 4; l++) {
            int s   = tid + l * 256;
            int row = s >> 4;
            int c4  = (s & 15) * 4;
            float4 kv = *(const float4*)(kbase + (size_t)(kt + row) * E3 + c4);
            ks[row * KPAD + c4 + 0] = kv.x; ks[row * KPAD + c4 + 1] = kv.y;
            ks[row * KPAD + c4 + 2] = kv.z; ks[row * KPAD + c4 + 3] = kv.w;
            float4 vv = *(const float4*)(vbase + (size_t)(kt + row) * E3 + c4);
            vs[row * VPAD + c4 + 0] = vv.x; vs[row * VPAD + c4 + 1] = vv.y;
            vs[row * VPAD + c4 + 2] = vv.z; vs[row * VPAD + c4 + 3] = vv.w;
        }
        __syncthreads();

        float sc[4][4];
#pragma unroll
        for (int i = 0; i < 4; i++)
#pragma unroll
            for (int j = 0; j < 4; j++) sc[i][j] = 0.0f;

#pragma unroll 8
        for (int d = 0; d < 64; d++) {
            float a[4], bb[4];
#pragma unroll
            for (int i = 0; i < 4; i++) a[i]  = qs[(r0 + i) * QPAD + d];
#pragma unroll
            for (int j = 0; j < 4; j++) bb[j] = ks[(c0 + j) * KPAD + d];
#pragma unroll
            for (int i = 0; i < 4; i++)
#pragma unroll
                for (int j = 0; j < 4; j++)
                    sc[i][j] += a[i] * bb[j];
        }
        __syncthreads();

#pragma unroll
        for (int i = 0; i < 4; i++) {
            float mx = fmaxf(fmaxf(sc[i][0], sc[i][1]), fmaxf(sc[i][2], sc[i][3]));
#pragma unroll
            for (int off = 8; off >= 1; off >>= 1)
                mx = fmaxf(mx, __shfl_xor_sync(0xffffffffu, mx, off, 32));
            float newm  = fmaxf(mrow[i], mx);
            float alpha = __expf(mrow[i] - newm);
            mrow[i] = newm;
            float rsum = 0.0f;
#pragma unroll
            for (int j = 0; j < 4; j++) {
                sc[i][j] = __expf(sc[i][j] - newm);
                rsum += sc[i][j];
            }
#pragma unroll
            for (int off = 8; off >= 1; off >>= 1)
                rsum += __shfl_xor_sync(0xffffffffu, rsum, off, 32);
            lrow[i] = lrow[i] * alpha + rsum;
#pragma unroll
            for (int j = 0; j < 4; j++) o[i][j] *= alpha;
        }

#pragma unroll
        for (int i = 0; i < 4; i++)
#pragma unroll
            for (int j = 0; j < 4; j++)
                ks[(r0 + i) * KPAD + c0 + j] = sc[i][j];
        __syncthreads();

#pragma unroll 8
        for (int k = 0; k < 64; k++) {
            float a[4], bb[4];
#pragma unroll
            for (int i = 0; i < 4; i++) a[i]  = ks[(r0 + i) * KPAD + k];
#pragma unroll
            for (int j = 0; j < 4; j++) bb[j] = vs[k * VPAD + c0 + j];
#pragma unroll
            for (int i = 0; i < 4; i++)
#pragma unroll
                for (int j = 0; j < 4; j++)
                    o[i][j] += a[i] * bb[j];
        }
    }

#pragma unroll
    for (int i = 0; i < 4; i++) {
        float inv = 1.0f / lrow[i];
        size_t base = (size_t)(b * SEQ + q0 + r0 + i) * EMB + h * HD + c0;
#pragma unroll
        for (int j = 0; j < 4; j++)
            ctx[base + j] = o[i][j] * inv;
    }
}

// ---------------------------------------------------------------------------
extern "C" void kernel_launch(void* const* d_in, const int* in_sizes, int n_in,
                              void* d_out, int out_size)
{
    const float* x      = (const float*)d_in[0];
    const float* w_qkv  = (const float*)d_in[1];
    const float* w_out  = (const float*)d_in[2];
    const float* b_qkv  = (const float*)d_in[3];
    const float* b_out  = (const float*)d_in[4];
    float* out = (float*)d_out;

    float *qkv_s = nullptr, *ctx_s = nullptr;
    cudaGetSymbolAddress((void**)&qkv_s, g_qkv);
    cudaGetSymbolAddress((void**)&ctx_s, g_ctx);

    cudaFuncSetAttribute(attn_kernel,
                         cudaFuncAttributeMaxDynamicSharedMemorySize, ATT_SMEM);

    // QKV projection: [4096,1024] @ [3072,1024]^T -> [4096,3072]
    gemm_mma_kernel<<<dim3(E3 / 128, MTOT / 128), 256>>>(
        x, w_qkv, b_qkv, qkv_s, MTOT, E3, EMB);

    // Attention
    attn_kernel<<<dim3(SEQ / 64, NH, BATCH), 256, ATT_SMEM>>>(qkv_s, ctx_s);

    // Output projection: [4096,1024] @ [1024,1024]^T -> [4096,1024]
    gemm_mma_kernel<<<dim3(EMB / 128, MTOT / 128), 256>>>(
        ctx_s, w_out, b_out, out, MTOT, EMB, EMB);
}

// round 4
// speedup vs baseline: 2.7219x; 1.7990x over previous
#include <cuda_runtime.h>
#include <cuda_bf16.h>
#include <cstdint>
#include <cstddef>

#define BATCH 2
#define SEQ   2048
#define EMB   1024
#define NH    16
#define HD    64
#define E3    (3*EMB)          // 3072
#define MTOT  (BATCH*SEQ)      // 4096
#define ATT_SCALE 0.125f       // 1/sqrt(64)

// Scratch (static device allocations are allowed)
__device__ float g_qkv[(size_t)MTOT * E3];   // [4096][3072]
__device__ float g_ctx[(size_t)MTOT * EMB];  // [4096][1024]

// ===========================================================================
// Warp-MMA helpers (non-'a' PTX: works on plain sm_103 target)
// ===========================================================================
__device__ __forceinline__ uint32_t cvta_smem(const void* p) {
    uint32_t a;
    asm("{ .reg .u64 t; cvta.to.shared.u64 t, %1; cvt.u32.u64 %0, t; }"
        : "=r"(a) : "l"(p));
    return a;
}

__device__ __forceinline__ void ldsm_x4(uint32_t& r0, uint32_t& r1,
                                        uint32_t& r2, uint32_t& r3, uint32_t addr) {
    asm volatile("ldmatrix.sync.aligned.m8n8.x4.shared.b16 {%0,%1,%2,%3}, [%4];"
                 : "=r"(r0), "=r"(r1), "=r"(r2), "=r"(r3) : "r"(addr));
}
__device__ __forceinline__ void ldsm_x2(uint32_t& r0, uint32_t& r1, uint32_t addr) {
    asm volatile("ldmatrix.sync.aligned.m8n8.x2.shared.b16 {%0,%1}, [%2];"
                 : "=r"(r0), "=r"(r1) : "r"(addr));
}
__device__ __forceinline__ void ldsm_x2_trans(uint32_t& r0, uint32_t& r1, uint32_t addr) {
    asm volatile("ldmatrix.sync.aligned.m8n8.x2.trans.shared.b16 {%0,%1}, [%2];"
                 : "=r"(r0), "=r"(r1) : "r"(addr));
}

__device__ __forceinline__ void mma_bf16(float* d, const uint32_t* a, const uint32_t* b) {
    asm volatile(
        "mma.sync.aligned.m16n8k16.row.col.f32.bf16.bf16.f32 "
        "{%0,%1,%2,%3}, {%4,%5,%6,%7}, {%8,%9}, {%0,%1,%2,%3};"
        : "+f"(d[0]), "+f"(d[1]), "+f"(d[2]), "+f"(d[3])
        : "r"(a[0]), "r"(a[1]), "r"(a[2]), "r"(a[3]), "r"(b[0]), "r"(b[1]));
}

// Pack two floats as bf16x2 (memory/register order: lo half = first arg)
__device__ __forceinline__ uint32_t pack_bf16x2(float a, float b) {
    uint32_t r;
    asm("cvt.rn.bf16x2.f32 %0, %1, %2;" : "=r"(r) : "f"(b), "f"(a));
    return r;
}
__device__ __forceinline__ float bf16_hi_val(float x) {
    uint32_t r;
    asm("{ .reg .b16 h; cvt.rn.bf16.f32 h, %1; mov.b32 %0, {h, h}; }" : "=r"(r) : "f"(x));
    return __uint_as_float(r & 0xFFFF0000u);
}

// ===========================================================================
// bf16-split GEMM (unchanged from R3): C = A @ W^T + bias
// ===========================================================================
#define SROW   40
#define TILE_B (128 * SROW * 2)
#define OFF_AHI 0
#define OFF_ALO (TILE_B)
#define OFF_BHI (2 * TILE_B)
#define OFF_BLO (3 * TILE_B)

__global__ __launch_bounds__(256)
void gemm_mma_kernel(const float* __restrict__ A, const float* __restrict__ W,
                     const float* __restrict__ bias, float* __restrict__ C,
                     int M, int N, int K)
{
    __shared__ __align__(16) char smem[4 * TILE_B];
    const uint32_t smem_u = cvta_smem(smem);

    const int tid  = threadIdx.x;
    const int wid  = tid >> 5;
    const int lane = tid & 31;
    const int wm   = wid & 3;
    const int wn   = wid >> 2;
    const int m0   = blockIdx.y * 128;
    const int n0   = blockIdx.x * 128;

    float acc[2][8][4];
#pragma unroll
    for (int mi = 0; mi < 2; mi++)
#pragma unroll
        for (int ni = 0; ni < 8; ni++)
#pragma unroll
            for (int r = 0; r < 4; r++) acc[mi][ni][r] = 0.0f;

    const int nchunks = K >> 5;
    float4 pA[4], pB[4];
    int lrow[4], lcol[4];
#pragma unroll
    for (int it = 0; it < 4; it++) {
        int idx = tid + it * 256;
        lrow[it] = idx >> 3;
        lcol[it] = (idx & 7) * 4;
    }
#pragma unroll 1
    for (int it = 0; it < 4; it++) {
        pA[it] = *(const float4*)(A + (size_t)(m0 + lrow[it]) * K + lcol[it]);
        pB[it] = *(const float4*)(W + (size_t)(n0 + lrow[it]) * K + lcol[it]);
    }

    for (int c = 0; c < nchunks; c++) {
        __syncthreads();
#pragma unroll
        for (int it = 0; it < 4; it++) {
            uint32_t base = (uint32_t)(lrow[it] * (SROW * 2) + lcol[it] * 2);
            float4 v = pA[it];
            float hx = bf16_hi_val(v.x), hy = bf16_hi_val(v.y);
            float hz = bf16_hi_val(v.z), hw = bf16_hi_val(v.w);
            uint2 hi = make_uint2(pack_bf16x2(hx, hy), pack_bf16x2(hz, hw));
            uint2 lo = make_uint2(pack_bf16x2(v.x - hx, v.y - hy),
                                  pack_bf16x2(v.z - hz, v.w - hw));
            *(uint2*)(smem + OFF_AHI + base) = hi;
            *(uint2*)(smem + OFF_ALO + base) = lo;

            v = pB[it];
            hx = bf16_hi_val(v.x); hy = bf16_hi_val(v.y);
            hz = bf16_hi_val(v.z); hw = bf16_hi_val(v.w);
            hi = make_uint2(pack_bf16x2(hx, hy), pack_bf16x2(hz, hw));
            lo = make_uint2(pack_bf16x2(v.x - hx, v.y - hy),
                            pack_bf16x2(v.z - hz, v.w - hw));
            *(uint2*)(smem + OFF_BHI + base) = hi;
            *(uint2*)(smem + OFF_BLO + base) = lo;
        }
        __syncthreads();

        if (c + 1 < nchunks) {
            const int k0 = (c + 1) << 5;
#pragma unroll
            for (int it = 0; it < 4; it++) {
                pA[it] = *(const float4*)(A + (size_t)(m0 + lrow[it]) * K + k0 + lcol[it]);
                pB[it] = *(const float4*)(W + (size_t)(n0 + lrow[it]) * K + k0 + lcol[it]);
            }
        }

#pragma unroll
        for (int ks = 0; ks < 2; ks++) {
            const uint32_t kbyte = (uint32_t)(ks * 16 * 2);
            uint32_t a_hi[2][4], a_lo[2][4];
#pragma unroll
            for (int mi = 0; mi < 2; mi++) {
                uint32_t arow = (uint32_t)(wm * 32 + mi * 16 + (lane & 15));
                uint32_t aoff = arow * (SROW * 2) + kbyte + ((lane >> 4) << 4);
                ldsm_x4(a_hi[mi][0], a_hi[mi][1], a_hi[mi][2], a_hi[mi][3],
                        smem_u + OFF_AHI + aoff);
                ldsm_x4(a_lo[mi][0], a_lo[mi][1], a_lo[mi][2], a_lo[mi][3],
                        smem_u + OFF_ALO + aoff);
            }
#pragma unroll
            for (int nh = 0; nh < 2; nh++) {
                uint32_t b_hi[4][2], b_lo[4][2];
#pragma unroll
                for (int nq = 0; nq < 4; nq++) {
                    uint32_t brow = (uint32_t)(wn * 64 + nh * 32 + nq * 8 + (lane & 7));
                    uint32_t boff = brow * (SROW * 2) + kbyte + (((lane >> 3) & 1) << 4);
                    ldsm_x2(b_hi[nq][0], b_hi[nq][1], smem_u + OFF_BHI + boff);
                    ldsm_x2(b_lo[nq][0], b_lo[nq][1], smem_u + OFF_BLO + boff);
                }
#pragma unroll
                for (int mi = 0; mi < 2; mi++)
#pragma unroll
                    for (int nq = 0; nq < 4; nq++) {
                        float* d = acc[mi][nh * 4 + nq];
                        mma_bf16(d, a_hi[mi], b_hi[nq]);
                        mma_bf16(d, a_hi[mi], b_lo[nq]);
                        mma_bf16(d, a_lo[mi], b_hi[nq]);
                    }
            }
        }
    }

    const int rbase = m0 + wm * 32 + (lane >> 2);
    const int cbase = n0 + wn * 64 + (lane & 3) * 2;
#pragma unroll
    for (int mi = 0; mi < 2; mi++) {
#pragma unroll
        for (int ni = 0; ni < 8; ni++) {
            int cc = cbase + ni * 8;
            float2 bv = *(const float2*)(bias + cc);
            int r = rbase + mi * 16;
            float2 o0 = make_float2(acc[mi][ni][0] + bv.x, acc[mi][ni][1] + bv.y);
            *(float2*)(C + (size_t)r * N + cc) = o0;
            float2 o1 = make_float2(acc[mi][ni][2] + bv.x, acc[mi][ni][3] + bv.y);
            *(float2*)(C + (size_t)(r + 8) * N + cc) = o1;
        }
    }
}

// ===========================================================================
// Tensor-core flash attention.
// CTA = (128-query tile, head, batch), 8 warps, warp = 16 query rows.
// K-tile = 64 keys. Q/K/V all split into bf16 hi+lo (3-term mma).
// smem rows padded to 72 bf16 (144B) -> ldmatrix conflict-free.
// ===========================================================================
#define AROWB 144                        // bytes per smem row (72 bf16)
#define AQHI  0
#define AQLO  (128 * AROWB)              // 18432
#define AKHI  (2 * 128 * AROWB)          // 36864
#define AKLO  (AKHI + 64 * AROWB)        // +9216
#define AVHI  (AKLO + 64 * AROWB)
#define AVLO  (AVHI + 64 * AROWB)
#define ATT_SMEM (AVLO + 64 * AROWB)     // 73728 bytes

__global__ __launch_bounds__(256)
void attn_mma_kernel(const float* __restrict__ qkv, float* __restrict__ ctx)
{
    extern __shared__ char sm[];
    const uint32_t smu = cvta_smem(sm);

    const int tid  = threadIdx.x;
    const int wid  = tid >> 5;
    const int lane = tid & 31;
    const int q0   = blockIdx.x * 128;
    const int h    = blockIdx.y;
    const int b    = blockIdx.z;

    const float* qbase = qkv + (size_t)(b * SEQ) * E3 + h * HD;
    const float* kbase = qbase + EMB;
    const float* vbase = qbase + 2 * EMB;

    // --- Load Q tile (128x64), pre-scale, split to bf16 hi/lo in smem ---
#pragma unroll
    for (int it = 0; it < 8; it++) {
        int idx = tid + it * 256;        // 0..2047
        int row = idx >> 4;
        int q4  = (idx & 15) * 4;
        float4 v = *(const float4*)(qbase + (size_t)(q0 + row) * E3 + q4);
        v.x *= ATT_SCALE; v.y *= ATT_SCALE; v.z *= ATT_SCALE; v.w *= ATT_SCALE;
        float hx = bf16_hi_val(v.x), hy = bf16_hi_val(v.y);
        float hz = bf16_hi_val(v.z), hw = bf16_hi_val(v.w);
        uint32_t base = (uint32_t)(row * AROWB + q4 * 2);
        *(uint2*)(sm + AQHI + base) = make_uint2(pack_bf16x2(hx, hy), pack_bf16x2(hz, hw));
        *(uint2*)(sm + AQLO + base) = make_uint2(pack_bf16x2(v.x - hx, v.y - hy),
                                                 pack_bf16x2(v.z - hz, v.w - hw));
    }
    __syncthreads();

    // --- Preload Q fragments into registers (warp rows: wid*16..+15) ---
    uint32_t qh[4][4], ql[4][4];
#pragma unroll
    for (int ks = 0; ks < 4; ks++) {
        uint32_t aoff = (uint32_t)((wid * 16 + (lane & 15)) * AROWB + ks * 32
                                   + ((lane >> 4) << 4));
        ldsm_x4(qh[ks][0], qh[ks][1], qh[ks][2], qh[ks][3], smu + AQHI + aoff);
        ldsm_x4(ql[ks][0], ql[ks][1], ql[ks][2], ql[ks][3], smu + AQLO + aoff);
    }

    float o[8][4];
#pragma unroll
    for (int nb = 0; nb < 8; nb++)
#pragma unroll
        for (int r = 0; r < 4; r++) o[nb][r] = 0.0f;
    float mrow[2] = { -1e30f, -1e30f };
    float lsum[2] = { 0.0f, 0.0f };

    // --- K/V tile prefetch registers ---
    float4 pK[4], pV[4];
    int krow[4], kq4[4];
#pragma unroll
    for (int it = 0; it < 4; it++) {
        int idx = tid + it * 256;        // 0..1023 (64 rows x 16 groups)
        krow[it] = idx >> 4;
        kq4[it]  = (idx & 15) * 4;
    }
#pragma unroll 1
    for (int it = 0; it < 4; it++) {
        pK[it] = *(const float4*)(kbase + (size_t)krow[it] * E3 + kq4[it]);
        pV[it] = *(const float4*)(vbase + (size_t)krow[it] * E3 + kq4[it]);
    }

    for (int kt = 0; kt < SEQ; kt += 64) {
        __syncthreads();     // previous tile fully consumed
#pragma unroll
        for (int it = 0; it < 4; it++) {
            uint32_t base = (uint32_t)(krow[it] * AROWB + kq4[it] * 2);
            float4 v = pK[it];
            float hx = bf16_hi_val(v.x), hy = bf16_hi_val(v.y);
            float hz = bf16_hi_val(v.z), hw = bf16_hi_val(v.w);
            *(uint2*)(sm + AKHI + base) = make_uint2(pack_bf16x2(hx, hy), pack_bf16x2(hz, hw));
            *(uint2*)(sm + AKLO + base) = make_uint2(pack_bf16x2(v.x - hx, v.y - hy),
                                                     pack_bf16x2(v.z - hz, v.w - hw));
            v = pV[it];
            hx = bf16_hi_val(v.x); hy = bf16_hi_val(v.y);
            hz = bf16_hi_val(v.z); hw = bf16_hi_val(v.w);
            *(uint2*)(sm + AVHI + base) = make_uint2(pack_bf16x2(hx, hy), pack_bf16x2(hz, hw));
            *(uint2*)(sm + AVLO + base) = make_uint2(pack_bf16x2(v.x - hx, v.y - hy),
                                                     pack_bf16x2(v.z - hz, v.w - hw));
        }
        __syncthreads();

        if (kt + 64 < SEQ) {
            const float* kb = kbase + (size_t)(kt + 64) * E3;
            const float* vb = vbase + (size_t)(kt + 64) * E3;
#pragma unroll
            for (int it = 0; it < 4; it++) {
                pK[it] = *(const float4*)(kb + (size_t)krow[it] * E3 + kq4[it]);
                pV[it] = *(const float4*)(vb + (size_t)krow[it] * E3 + kq4[it]);
            }
        }

        // --- scores = Q @ K^T  (16 rows x 64 keys per warp) ---
        float sc[8][4];
#pragma unroll
        for (int nb = 0; nb < 8; nb++)
#pragma unroll
            for (int r = 0; r < 4; r++) sc[nb][r] = 0.0f;

#pragma unroll
        for (int nb = 0; nb < 8; nb++) {
#pragma unroll
            for (int ks = 0; ks < 4; ks++) {
                uint32_t brow = (uint32_t)(nb * 8 + (lane & 7));
                uint32_t boff = brow * AROWB + ks * 32 + (((lane >> 3) & 1) << 4);
                uint32_t kh[2], kl[2];
                ldsm_x2(kh[0], kh[1], smu + AKHI + boff);
                ldsm_x2(kl[0], kl[1], smu + AKLO + boff);
                mma_bf16(sc[nb], qh[ks], kh);
                mma_bf16(sc[nb], qh[ks], kl);
                mma_bf16(sc[nb], ql[ks], kh);
            }
        }

        // --- online softmax (rows r = lane>>2 and r+8; reduce over 4-lane group) ---
#pragma unroll
        for (int u = 0; u < 2; u++) {
            float rmax = -1e30f;
#pragma unroll
            for (int nb = 0; nb < 8; nb++)
                rmax = fmaxf(rmax, fmaxf(sc[nb][2 * u], sc[nb][2 * u + 1]));
            rmax = fmaxf(rmax, __shfl_xor_sync(0xffffffffu, rmax, 1, 32));
            rmax = fmaxf(rmax, __shfl_xor_sync(0xffffffffu, rmax, 2, 32));
            float newm  = fmaxf(mrow[u], rmax);
            float alpha = __expf(mrow[u] - newm);
            mrow[u] = newm;
            float rsum = 0.0f;
#pragma unroll
            for (int nb = 0; nb < 8; nb++) {
                sc[nb][2 * u]     = __expf(sc[nb][2 * u]     - newm);
                sc[nb][2 * u + 1] = __expf(sc[nb][2 * u + 1] - newm);
                rsum += sc[nb][2 * u] + sc[nb][2 * u + 1];
            }
            rsum += __shfl_xor_sync(0xffffffffu, rsum, 1, 32);
            rsum += __shfl_xor_sync(0xffffffffu, rsum, 2, 32);
            lsum[u] = lsum[u] * alpha + rsum;
#pragma unroll
            for (int nb = 0; nb < 8; nb++) {
                o[nb][2 * u]     *= alpha;
                o[nb][2 * u + 1] *= alpha;
            }
        }

        // --- O += P @ V  (P fragments built directly from score registers) ---
#pragma unroll
        for (int ks = 0; ks < 4; ks++) {
            const int b0 = 2 * ks, b1 = 2 * ks + 1;
            uint32_t ph[4], pl[4];
            {
                float h0 = bf16_hi_val(sc[b0][0]), h1 = bf16_hi_val(sc[b0][1]);
                float h2 = bf16_hi_val(sc[b0][2]), h3 = bf16_hi_val(sc[b0][3]);
                ph[0] = pack_bf16x2(h0, h1);
                ph[1] = pack_bf16x2(h2, h3);
                pl[0] = pack_bf16x2(sc[b0][0] - h0, sc[b0][1] - h1);
                pl[1] = pack_bf16x2(sc[b0][2] - h2, sc[b0][3] - h3);
                h0 = bf16_hi_val(sc[b1][0]); h1 = bf16_hi_val(sc[b1][1]);
                h2 = bf16_hi_val(sc[b1][2]); h3 = bf16_hi_val(sc[b1][3]);
                ph[2] = pack_bf16x2(h0, h1);
                ph[3] = pack_bf16x2(h2, h3);
                pl[2] = pack_bf16x2(sc[b1][0] - h0, sc[b1][1] - h1);
                pl[3] = pack_bf16x2(sc[b1][2] - h2, sc[b1][3] - h3);
            }
#pragma unroll
            for (int nb = 0; nb < 8; nb++) {
                uint32_t srow = (uint32_t)(ks * 16 + (lane & 7) + 8 * ((lane >> 3) & 1));
                uint32_t voff = srow * AROWB + nb * 16;
                uint32_t vh[2], vl[2];
                ldsm_x2_trans(vh[0], vh[1], smu + AVHI + voff);
                ldsm_x2_trans(vl[0], vl[1], smu + AVLO + voff);
                mma_bf16(o[nb], ph, vh);
                mma_bf16(o[nb], ph, vl);
                mma_bf16(o[nb], pl, vh);
            }
        }
    }

    // --- epilogue: normalize, write ctx[b*S + row][h*64 + col] ---
    const float inv0 = 1.0f / lsum[0];
    const float inv1 = 1.0f / lsum[1];
    const int row0 = q0 + wid * 16 + (lane >> 2);
    const int col0 = h * HD + (lane & 3) * 2;
#pragma unroll
    for (int nb = 0; nb < 8; nb++) {
        int cc = col0 + nb * 8;
        *(float2*)(ctx + (size_t)(b * SEQ + row0) * EMB + cc) =
            make_float2(o[nb][0] * inv0, o[nb][1] * inv0);
        *(float2*)(ctx + (size_t)(b * SEQ + row0 + 8) * EMB + cc) =
            make_float2(o[nb][2] * inv1, o[nb][3] * inv1);
    }
}

// ---------------------------------------------------------------------------
extern "C" void kernel_launch(void* const* d_in, const int* in_sizes, int n_in,
                              void* d_out, int out_size)
{
    const float* x      = (const float*)d_in[0];
    const float* w_qkv  = (const float*)d_in[1];
    const float* w_out  = (const float*)d_in[2];
    const float* b_qkv  = (const float*)d_in[3];
    const float* b_out  = (const float*)d_in[4];
    float* out = (float*)d_out;

    float *qkv_s = nullptr, *ctx_s = nullptr;
    cudaGetSymbolAddress((void**)&qkv_s, g_qkv);
    cudaGetSymbolAddress((void**)&ctx_s, g_ctx);

    cudaFuncSetAttribute(attn_mma_kernel,
                         cudaFuncAttributeMaxDynamicSharedMemorySize, ATT_SMEM);

    // QKV projection: [4096,1024] @ [3072,1024]^T -> [4096,3072]
    gemm_mma_kernel<<<dim3(E3 / 128, MTOT / 128), 256>>>(
        x, w_qkv, b_qkv, qkv_s, MTOT, E3, EMB);

    // Attention (tensor-core flash)
    attn_mma_kernel<<<dim3(SEQ / 128, NH, BATCH), 256, ATT_SMEM>>>(qkv_s, ctx_s);

    // Output projection: [4096,1024] @ [1024,1024]^T -> [4096,1024]
    gemm_mma_kernel<<<dim3(EMB / 128, MTOT / 128), 256>>>(
        ctx_s, w_out, b_out, out, MTOT, EMB, EMB);
}